// round 12
// baseline (speedup 1.0000x reference)
#include <cuda_runtime.h>
#include <cuda_fp16.h>
#include <cstdint>
#include <math.h>

#define B_  128
#define F_  1024
#define W_  32
#define H_  64
#define G_  256
#define NCH 64           // k16 chunks

#define AP  40           // A smem row pitch (fp16): conflict-free ldmatrix
#define SMEM_DYN (F_ * AP * 2)   // 81920 B

using u64 = unsigned long long;

// B packed fp16 fragments, n-tile-pair major:
// [chunk][pair(=warp)][lane] -> uint4{ t0.b0, t0.b1, t1.b0, t1.b1 }, tiles 2p, 2p+1
__device__ uint4 g_wxp[NCH * 16 * 32];

__device__ __forceinline__ uint32_t smem_u32(const void* p) {
    return (uint32_t)__cvta_generic_to_shared(p);
}
__device__ __forceinline__ void ldm4t(uint32_t* r, uint32_t addr) {
    asm volatile("ldmatrix.sync.aligned.m8n8.x4.trans.shared.b16 {%0,%1,%2,%3}, [%4];"
                 : "=r"(r[0]), "=r"(r[1]), "=r"(r[2]), "=r"(r[3]) : "r"(addr));
}
__device__ __forceinline__ void mma_f16(float* d, const uint32_t* a, uint32_t b0, uint32_t b1) {
    asm volatile("mma.sync.aligned.m16n8k16.row.col.f32.f16.f16.f32 "
                 "{%0,%1,%2,%3}, {%4,%5,%6,%7}, {%8,%9}, {%0,%1,%2,%3};"
                 : "+f"(d[0]), "+f"(d[1]), "+f"(d[2]), "+f"(d[3])
                 : "r"(a[0]), "r"(a[1]), "r"(a[2]), "r"(a[3]), "r"(b0), "r"(b1));
}
__device__ __forceinline__ u64 fma2(u64 a, u64 b, u64 c) {
    u64 d; asm("fma.rn.f32x2 %0, %1, %2, %3;" : "=l"(d) : "l"(a), "l"(b), "l"(c)); return d;
}
__device__ __forceinline__ u64 add2(u64 a, u64 b) {
    u64 d; asm("add.rn.f32x2 %0, %1, %2;" : "=l"(d) : "l"(a), "l"(b)); return d;
}
__device__ __forceinline__ u64 pack2(float lo, float hi) {
    u64 d; asm("mov.b64 %0, {%1, %2};" : "=l"(d)
               : "r"(__float_as_uint(lo)), "r"(__float_as_uint(hi)));
    return d;
}
__device__ __forceinline__ float2 unpack2(u64 a) {
    unsigned lo, hi; asm("mov.b64 {%0, %1}, %2;" : "=r"(lo), "=r"(hi) : "l"(a));
    return make_float2(__uint_as_float(lo), __uint_as_float(hi));
}
__device__ __forceinline__ uint32_t packh(float a, float b) {
    __half2 h = __floats2half2_rn(a, b);       // low = a, high = b
    return *(uint32_t*)&h;
}

// ---------------------------------------------------------------------------
// Pre-kernel: Wx fp32 -> packed fp16 B-fragments (pair layout). One block per
// k16 chunk (grid 64): stage 16x256 fp32 (16 KB), emit 512 uint4 entries.
// ---------------------------------------------------------------------------
extern "C" __global__ void __launch_bounds__(256)
conv_wx_kernel(const float* __restrict__ Wx)
{
    __shared__ float sw[16 * 256];
    const int ch  = blockIdx.x;
    const int tid = threadIdx.x;

    const float* src = Wx + (size_t)ch * 16 * G_;
#pragma unroll
    for (int seg = 0; seg < 4; ++seg) {
        int i = (seg * 256 + tid) * 4;
        *(float4*)(sw + i) = *(const float4*)(src + i);
    }
    __syncthreads();

#pragma unroll
    for (int e = 0; e < 2; ++e) {
        int ent  = e * 256 + tid;           // 0..511
        int p    = ent >> 5;                // n-tile pair 0..15
        int lane = ent & 31;
        int n0   = p * 16 + (lane >> 2);    // tile 2p
        int n1   = n0 + 8;                  // tile 2p+1
        int k0   = 2 * (lane & 3);

        uint4 v;
        v.x = packh(sw[(k0    ) * G_ + n0], sw[(k0 + 1) * G_ + n0]);
        v.y = packh(sw[(k0 + 8) * G_ + n0], sw[(k0 + 9) * G_ + n0]);
        v.z = packh(sw[(k0    ) * G_ + n1], sw[(k0 + 1) * G_ + n1]);
        v.w = packh(sw[(k0 + 8) * G_ + n1], sw[(k0 + 9) * G_ + n1]);
        g_wxp[(size_t)ch * 512 + ent] = v;
    }
}

// ---------------------------------------------------------------------------
// Fused kernel: 1 block per batch, 512 threads (16 warps).
//  Phase 1: fp16 GEMM  Xp[t,g] = sum_f x[b,f,t]*Wx[f,g]
//   (softmax over the size-1 axis == 1 -> attention branch is dead code;
//    fp16 x fp16 -> fp32 accum, analytic rel err ~4e-4 < 1e-3 gate)
//   Warp w owns the FULL k (64 chunks) for n-cols [16w, 16w+16): m32 x n16.
//   No split-K. Depth-4 register ring for B (LDG.128/chunk), distance-1
//   ping-pong for A fragments (ldmatrix from the 80 KB staged A).
//   First 4 B loads issue before the A prologue to hide cold L2 latency.
//  Phase 2: LSTM recurrence on warps 0-7; output = CELL state.
// ---------------------------------------------------------------------------
extern "C" __global__ void __launch_bounds__(512, 1)
attn_rnn_tc(const float* __restrict__ x,  const float* __restrict__ Wh,
            const float* __restrict__ b_lstm, float* __restrict__ out)
{
    extern __shared__ __align__(16) __half sA[];   // [F_][AP] fp16 ; later gate tile
    __shared__ __align__(16) float h_s[2][H_];

    const int b    = blockIdx.x;
    const int tid  = threadIdx.x;
    const int w    = tid >> 5;
    const int lane = tid & 31;

    const float* xb = x + (size_t)b * F_ * W_;

    // ---- B ring preload (issues before prologue; hides cold L2 trip) ----
    const uint4* bsrc = g_wxp + ((size_t)w * 32) + lane;
    uint4 bq[4];
#pragma unroll
    for (int i = 0; i < 4; ++i)
        bq[i] = bsrc[(size_t)i * 512];

    // ---- Prologue: stage all of A (fp16) ----
    {
        const int rbase = tid >> 4;           // 0..31
        const int tc    = (tid & 15) * 2;     // t column pair
#pragma unroll 4
        for (int seg = 0; seg < 32; ++seg) {
            int f = rbase + 32 * seg;
            float2 v = *(const float2*)(xb + (size_t)f * W_ + tc);
            *(__half2*)(sA + f * AP + tc) = __floats2half2_rn(v.x, v.y);
        }
    }
    __syncthreads();

    float acc[2][2][4];      // [mt][nt][4]
#pragma unroll
    for (int mt = 0; mt < 2; ++mt)
#pragma unroll
        for (int nt = 0; nt < 2; ++nt)
#pragma unroll
            for (int i = 0; i < 4; ++i) acc[mt][nt][i] = 0.f;

    // ldmatrix lane addressing (within a chunk)
    const int lr = lane & 7, lg = lane >> 3;
    const int akq = (lg & 2) ? (8 + lr) : lr;
    const int amo = (lg & 1) ? 8 : 0;

    uint32_t ah[2][2][4];    // [pingpong][mt][4]
#pragma unroll
    for (int mt = 0; mt < 2; ++mt)
        ldm4t(ah[0][mt], smem_u32(sA + akq * AP + 16 * mt + amo));

#pragma unroll 4
    for (int c = 0; c < NCH; ++c) {
        int cl = (c + 4 < NCH) ? (c + 4) : (NCH - 1);
        uint4 bn = bsrc[(size_t)cl * 512];

        int cn = (c + 1 < NCH) ? (c + 1) : (NCH - 1);
        int fb = cn * 16 + akq;
#pragma unroll
        for (int mt = 0; mt < 2; ++mt)
            ldm4t(ah[(c + 1) & 1][mt], smem_u32(sA + fb * AP + 16 * mt + amo));

        uint4 bc = bq[c & 3];
        mma_f16(acc[0][0], ah[c & 1][0], bc.x, bc.y);
        mma_f16(acc[1][0], ah[c & 1][1], bc.x, bc.y);
        mma_f16(acc[0][1], ah[c & 1][0], bc.z, bc.w);
        mma_f16(acc[1][1], ah[c & 1][1], bc.z, bc.w);

        bq[c & 3] = bn;
    }
    __syncthreads();     // all warps done reading A before gate tile overwrites it

    // ---- write accumulators into gate tile [32][256] fp32 (disjoint cols) ----
    float* xp = (float*)sA;
    const int r0 = lane >> 2, c0 = 2 * (lane & 3);
#pragma unroll
    for (int mt = 0; mt < 2; ++mt)
#pragma unroll
        for (int nt = 0; nt < 2; ++nt) {
            int n = 16 * w + 8 * nt;
            *(float2*)(xp + (16 * mt + r0) * G_ + n + c0)     = make_float2(acc[mt][nt][0], acc[mt][nt][1]);
            *(float2*)(xp + (16 * mt + r0 + 8) * G_ + n + c0) = make_float2(acc[mt][nt][2], acc[mt][nt][3]);
        }
    __syncthreads();

    // ---------------- Phase 2: LSTM recurrence (warps 0-7 only) ----------------
    if (tid >= 256) return;

    const int q   = lane >> 3;
    const int r   = lane & 7;
    const int idx = 8 * w + r;
    const int col = q * 64 + idx;

    u64 whp[H_ / 2];
#pragma unroll
    for (int m = 0; m < H_ / 2; ++m)
        whp[m] = pack2(Wh[(2 * m) * G_ + col], Wh[(2 * m + 1) * G_ + col]);
    const float bj = b_lstm[col];

    if (tid < H_) h_s[0][tid] = 0.f;
    float c_st = 0.f;
    float* ob = out + (size_t)b * W_ * H_;
    asm volatile("bar.sync 1, 256;" ::: "memory");

    int p = 0;
    for (int t = 0; t < W_; ++t) {
        const u64* hp = (const u64*)h_s[p];
        u64 a0 = 0ull, a1 = 0ull, a2 = 0ull, a3 = 0ull;
#pragma unroll
        for (int m = 0; m < H_ / 2; m += 4) {
            a0 = fma2(hp[m + 0], whp[m + 0], a0);
            a1 = fma2(hp[m + 1], whp[m + 1], a1);
            a2 = fma2(hp[m + 2], whp[m + 2], a2);
            a3 = fma2(hp[m + 3], whp[m + 3], a3);
        }
        float2 s2 = unpack2(add2(add2(a0, a1), add2(a2, a3)));
        float g = s2.x + s2.y + xp[t * G_ + col] + bj;

        float sc  = (q == 2) ? -2.f : -1.f;
        float e   = __expf(sc * g);
        float num = (q == 2) ? (1.f - e) : 1.f;
        float act = __fdividef(num, 1.f + e);

        float ai = __shfl_sync(0xffffffffu, act, r);
        float af = __shfl_sync(0xffffffffu, act, 8 + r);
        float ag = __shfl_sync(0xffffffffu, act, 16 + r);
        float ao = __shfl_sync(0xffffffffu, act, 24 + r);

        c_st = fmaf(af, c_st, ai * ag);
        float e2 = __expf(-2.f * c_st);
        float th = __fdividef(1.f - e2, 1.f + e2);

        if (q == 0) {
            h_s[p ^ 1][idx] = ao * th;
            ob[t * H_ + idx] = c_st;              // reference emits the CELL state
        }
        p ^= 1;
        asm volatile("bar.sync 1, 256;" ::: "memory");
    }
}

// ---------------------------------------------------------------------------
extern "C" void kernel_launch(void* const* d_in, const int* in_sizes, int n_in,
                              void* d_out, int out_size)
{
    const float* x      = (const float*)d_in[0];
    const float* Wx     = (const float*)d_in[6];
    const float* Wh     = (const float*)d_in[7];
    const float* b_lstm = (const float*)d_in[8];
    float*       out    = (float*)d_out;

    cudaFuncSetAttribute(attn_rnn_tc, cudaFuncAttributeMaxDynamicSharedMemorySize, SMEM_DYN);

    conv_wx_kernel<<<NCH, 256>>>(Wx);
    attn_rnn_tc<<<B_, 512, SMEM_DYN>>>(x, Wh, b_lstm, out);
}